// round 8
// baseline (speedup 1.0000x reference)
#include <cuda_runtime.h>
#include <math_constants.h>

#define BB 4
#define TT 4096
#define DD 1024
#define NROW (BB*TT)          // 16384

// ---- scratch (device globals: no allocations allowed) ----
__device__ float2 g_Q[NROW];
__device__ float2 g_K[NROW];
__device__ unsigned long long g_best64[NROW]; // (ordered(score)<<32)|~s
__device__ int    g_idx[NROW];      // flattened source row b*T + argmax_s
__device__ int    g_mark[NROW];
__device__ int    g_slot[NROW];     // src row -> compact slot
__device__ int    g_list[NROW];
__device__ int    g_count;
__device__ float  g_Vc[(size_t)NROW * DD];  // compact V rows (slot-major)

static const unsigned FULL = 0xffffffffu;

__device__ __forceinline__ unsigned ord_f32(float x) {
    unsigned u = __float_as_uint(x);
    return (u & 0x80000000u) ? ~u : (u | 0x80000000u);
}

// ---------------- kernel 1: Q,K projection (+ fused scratch init) ----------
__global__ void qk_kernel(const float* __restrict__ x,
                          const float* __restrict__ WQ,
                          const float* __restrict__ WK) {
    __shared__ float4 swq0[256], swq1[256], swk0[256], swk1[256];
    const float4* WQ4 = (const float4*)WQ;
    const float4* WK4 = (const float4*)WK;
    int tid = threadIdx.x;
    swq0[tid] = WQ4[tid];
    swq1[tid] = WQ4[256 + tid];
    swk0[tid] = WK4[tid];
    swk1[tid] = WK4[256 + tid];
    __syncthreads();

    int warp = tid >> 5, lane = tid & 31;
    int row = blockIdx.x * 8 + warp;           // b*T + t
    const float4* x4 = (const float4*)x + (size_t)row * 256;

    float q0 = 0.f, q1 = 0.f, k0 = 0.f, k1 = 0.f;
#pragma unroll
    for (int j = 0; j < 8; ++j) {
        int d = lane + j * 32;
        float4 xv = x4[d];
        float4 a = swq0[d], b = swq1[d], c = swk0[d], e = swk1[d];
        q0 += xv.x*a.x + xv.y*a.y + xv.z*a.z + xv.w*a.w;
        q1 += xv.x*b.x + xv.y*b.y + xv.z*b.z + xv.w*b.w;
        k0 += xv.x*c.x + xv.y*c.y + xv.z*c.z + xv.w*c.w;
        k1 += xv.x*e.x + xv.y*e.y + xv.z*e.z + xv.w*e.w;
    }
#pragma unroll
    for (int off = 16; off; off >>= 1) {
        q0 += __shfl_xor_sync(FULL, q0, off);
        q1 += __shfl_xor_sync(FULL, q1, off);
        k0 += __shfl_xor_sync(FULL, k0, off);
        k1 += __shfl_xor_sync(FULL, k1, off);
    }
    if (lane == 0) {
        g_Q[row] = make_float2(q0, q1);
        g_K[row] = make_float2(k0, k1);
        g_mark[row] = 0;
        g_best64[row] = 0ull;                  // < any real score encoding
        if (row == 0) g_count = 0;
    }
}

// ---------------- kernel 2: argmax, tile x chunk units ----------------
// Unit = (128-t tile, 1024-s chunk). 80 units/batch, grid (80, BB), 128 thr.
// Merge via atomicMax of (ordered(score)<<32)|~s  -> max score, min s on tie.
__global__ void __launch_bounds__(128) argmax_kernel() {
    __shared__ float2 ks[1024];    // 8 KB
    int b = blockIdx.y;
    int u = blockIdx.x, g = 0, base = 0;
    while (u >= base + 8 * (g + 1)) { base += 8 * (g + 1); ++g; }
    int r = u - base;
    int ti = g * 8 + r / (g + 1);
    int chunk = r % (g + 1);
    int t0 = ti * 128, s0 = chunk * 1024;

    const float4* K4 = (const float4*)(g_K + b * TT + s0);
#pragma unroll
    for (int j = 0; j < 4; ++j)
        ((float4*)ks)[threadIdx.x + j * 128] = K4[threadIdx.x + j * 128];
    __syncthreads();

    int t = t0 + threadIdx.x;
    float2 q = g_Q[b * TT + t];
    int s_limit = t - s0 + 1;
    if (s_limit > 1024) s_limit = 1024;

    float best = -CUDART_INF_F;
    int bi = 0;
    for (int s = 0; s < s_limit; ++s) {        // ascending + strict > = first occ.
        float2 k = ks[s];
        float sc = k.x * q.x + k.y * q.y;
        if (sc > best) { best = sc; bi = s0 + s; }
    }
    unsigned long long enc =
        ((unsigned long long)ord_f32(best) << 32) | (unsigned)(~bi);
    atomicMax(&g_best64[b * TT + t], enc);
}

// ---------------- kernel 2b: decode argmax + build unique list -------------
__global__ void decode_kernel() {
    int i = blockIdx.x * 256 + threadIdx.x;
    if (i >= NROW) return;
    unsigned long long enc = g_best64[i];
    int s = (int)(~(unsigned)(enc & 0xffffffffull));
    int src = (i & ~(TT - 1)) | s;
    g_idx[i] = src;
    if (atomicExch(&g_mark[src], 1) == 0) {
        int p = atomicAdd(&g_count, 1);
        g_list[p] = src;
        g_slot[src] = p;                       // read only by later kernels
    }
}

// ---------------- kernel 3: V rows, register-resident W_V ----------------
// Item = (e-octet, 8-row group): 128 * ceil(cnt/8) items (~1024), grid 1024.
// Warp owns ONE e-row of W_V in registers (8 float4); loops 8 unique rows:
// 8 independent x LDG.128 + 32 FFMA (4 partial chains) + 5-SHFL reduce + STG.
// No smem, no block syncs -> high co-residency, latency-tolerant.
#define RG 8
__global__ void __launch_bounds__(256) vrows_kernel(const float* __restrict__ WV,
                                                    const float* __restrict__ x) {
    int cnt = g_count;
    int nrg = (cnt + RG - 1) / RG;
    int items = 128 * nrg;
    int warp = threadIdx.x >> 5, lane = threadIdx.x & 31;

    for (int it = blockIdx.x; it < items; it += gridDim.x) {
        int eo = it / nrg;                 // e-octet 0..127
        int rg = it - eo * nrg;            // row group
        int e  = eo * 8 + warp;

        const float4* wp = (const float4*)WV + (size_t)e * 256;
        float4 w[8];
#pragma unroll
        for (int j = 0; j < 8; ++j)
            w[j] = __ldg(&wp[lane + j * 32]);

        int ui0 = rg * RG;
#pragma unroll
        for (int r = 0; r < RG; ++r) {
            int ui = ui0 + r;
            if (ui >= cnt) break;
            int row = g_list[ui];
            const float4* xr = (const float4*)x + (size_t)row * 256;

            float4 x0 = __ldg(&xr[lane +   0]);
            float4 x1 = __ldg(&xr[lane +  32]);
            float4 x2 = __ldg(&xr[lane +  64]);
            float4 x3 = __ldg(&xr[lane +  96]);
            float4 x4 = __ldg(&xr[lane + 128]);
            float4 x5 = __ldg(&xr[lane + 160]);
            float4 x6 = __ldg(&xr[lane + 192]);
            float4 x7 = __ldg(&xr[lane + 224]);

            float a0 = w[0].x*x0.x + w[0].y*x0.y + w[0].z*x0.z + w[0].w*x0.w;
            float a1 = w[1].x*x1.x + w[1].y*x1.y + w[1].z*x1.z + w[1].w*x1.w;
            float a2 = w[2].x*x2.x + w[2].y*x2.y + w[2].z*x2.z + w[2].w*x2.w;
            float a3 = w[3].x*x3.x + w[3].y*x3.y + w[3].z*x3.z + w[3].w*x3.w;
            a0 += w[4].x*x4.x + w[4].y*x4.y + w[4].z*x4.z + w[4].w*x4.w;
            a1 += w[5].x*x5.x + w[5].y*x5.y + w[5].z*x5.z + w[5].w*x5.w;
            a2 += w[6].x*x6.x + w[6].y*x6.y + w[6].z*x6.z + w[6].w*x6.w;
            a3 += w[7].x*x7.x + w[7].y*x7.y + w[7].z*x7.z + w[7].w*x7.w;
            float a = (a0 + a1) + (a2 + a3);
#pragma unroll
            for (int off = 16; off; off >>= 1)
                a += __shfl_xor_sync(FULL, a, off);
            if (lane == 0)
                g_Vc[(size_t)ui * DD + e] = a;
        }
    }
}

// ---------------- kernel 4: gather to output ----------------
// Warp copies one 4KB row from compact (L2-resident) V; streaming stores.
__global__ void gather_kernel(float* __restrict__ out) {
    int warp = threadIdx.x >> 5, lane = threadIdx.x & 31;
    int r = blockIdx.x * 8 + warp;          // destination row b*T + t
    int slot = g_slot[g_idx[r]];
    const float4* v4 = (const float4*)g_Vc + (size_t)slot * 256;
    float4* o4 = (float4*)out + (size_t)r * 256;
#pragma unroll
    for (int j = 0; j < 8; ++j) {
        float4 v = __ldg(&v4[lane + j * 32]);
        __stcs(&o4[lane + j * 32], v);
    }
}

extern "C" void kernel_launch(void* const* d_in, const int* in_sizes, int n_in,
                              void* d_out, int out_size) {
    const float* x  = (const float*)d_in[0];
    const float* WQ = (const float*)d_in[1];
    const float* WK = (const float*)d_in[2];
    const float* WV = (const float*)d_in[3];
    float* out = (float*)d_out;

    qk_kernel<<<NROW / 8, 256>>>(x, WQ, WK);
    argmax_kernel<<<dim3(80, BB), 128>>>();
    decode_kernel<<<NROW / 256, 256>>>();
    vrows_kernel<<<1024, 256>>>(WV, x);
    gather_kernel<<<NROW / 8, 256>>>(out);
}

// round 9
// speedup vs baseline: 1.0061x; 1.0061x over previous
#include <cuda_runtime.h>
#include <math_constants.h>

#define BB 4
#define TT 4096
#define DD 1024
#define NROW (BB*TT)          // 16384
#define SLOTS 1024            // max unique rows supported (measured ~64)

// ---- scratch (device globals: no allocations allowed) ----
__device__ float2 g_Q[NROW];
__device__ float2 g_K[NROW];
__device__ unsigned long long g_best64[NROW]; // (ordered(score)<<32)|~s
__device__ int    g_idx[NROW];      // flattened source row b*T + argmax_s
__device__ int    g_mark[NROW];
__device__ int    g_slot[NROW];     // src row -> compact slot
__device__ int    g_list[SLOTS];
__device__ int    g_count;
__device__ float  g_WVt[DD * DD];            // 4 MB, W_V transposed [k][e]
__device__ float  g_Vp[4][(size_t)SLOTS * DD]; // 16 MB, k-quarter partials
__device__ float  g_Vc[(size_t)SLOTS * DD];  // 4 MB, compact V rows

static const unsigned FULL = 0xffffffffu;

__device__ __forceinline__ unsigned ord_f32(float x) {
    unsigned u = __float_as_uint(x);
    return (u & 0x80000000u) ? ~u : (u | 0x80000000u);
}

// ---------------- kernel 0: transpose W_V -> WVt[k][e] ----------------
__global__ void transpose_kernel(const float* __restrict__ WV) {
    __shared__ float t[32][33];
    int bx = blockIdx.x * 32;   // e base
    int by = blockIdx.y * 32;   // k base
    int tx = threadIdx.x, ty = threadIdx.y;
#pragma unroll
    for (int i = 0; i < 4; ++i)
        t[ty + i * 8][tx] = WV[(size_t)(bx + ty + i * 8) * DD + by + tx];
    __syncthreads();
#pragma unroll
    for (int i = 0; i < 4; ++i)
        g_WVt[(size_t)(by + ty + i * 8) * DD + bx + tx] = t[tx][ty + i * 8];
}

// ---------------- kernel 1: Q,K projection (+ fused scratch init) ----------
__global__ void qk_kernel(const float* __restrict__ x,
                          const float* __restrict__ WQ,
                          const float* __restrict__ WK) {
    __shared__ float4 swq0[256], swq1[256], swk0[256], swk1[256];
    const float4* WQ4 = (const float4*)WQ;
    const float4* WK4 = (const float4*)WK;
    int tid = threadIdx.x;
    swq0[tid] = WQ4[tid];
    swq1[tid] = WQ4[256 + tid];
    swk0[tid] = WK4[tid];
    swk1[tid] = WK4[256 + tid];
    __syncthreads();

    int warp = tid >> 5, lane = tid & 31;
    int row = blockIdx.x * 8 + warp;           // b*T + t
    const float4* x4 = (const float4*)x + (size_t)row * 256;

    float q0 = 0.f, q1 = 0.f, k0 = 0.f, k1 = 0.f;
#pragma unroll
    for (int j = 0; j < 8; ++j) {
        int d = lane + j * 32;
        float4 xv = x4[d];
        float4 a = swq0[d], b = swq1[d], c = swk0[d], e = swk1[d];
        q0 += xv.x*a.x + xv.y*a.y + xv.z*a.z + xv.w*a.w;
        q1 += xv.x*b.x + xv.y*b.y + xv.z*b.z + xv.w*b.w;
        k0 += xv.x*c.x + xv.y*c.y + xv.z*c.z + xv.w*c.w;
        k1 += xv.x*e.x + xv.y*e.y + xv.z*e.z + xv.w*e.w;
    }
#pragma unroll
    for (int off = 16; off; off >>= 1) {
        q0 += __shfl_xor_sync(FULL, q0, off);
        q1 += __shfl_xor_sync(FULL, q1, off);
        k0 += __shfl_xor_sync(FULL, k0, off);
        k1 += __shfl_xor_sync(FULL, k1, off);
    }
    if (lane == 0) {
        g_Q[row] = make_float2(q0, q1);
        g_K[row] = make_float2(k0, k1);
        g_mark[row] = 0;
        g_best64[row] = 0ull;                  // < any real score encoding
        if (row == 0) g_count = 0;
    }
}

// ---------------- kernel 2: argmax, tile x chunk units ----------------
// Unit = (128-t tile, 1024-s chunk). 80 units/batch, grid (80, BB), 128 thr.
// Merge via atomicMax of (ordered(score)<<32)|~s  -> max score, min s on tie.
__global__ void __launch_bounds__(128) argmax_kernel() {
    __shared__ float2 ks[1024];    // 8 KB
    int b = blockIdx.y;
    int u = blockIdx.x, g = 0, base = 0;
    while (u >= base + 8 * (g + 1)) { base += 8 * (g + 1); ++g; }
    int r = u - base;
    int ti = g * 8 + r / (g + 1);
    int chunk = r % (g + 1);
    int t0 = ti * 128, s0 = chunk * 1024;

    const float4* K4 = (const float4*)(g_K + b * TT + s0);
#pragma unroll
    for (int j = 0; j < 4; ++j)
        ((float4*)ks)[threadIdx.x + j * 128] = K4[threadIdx.x + j * 128];
    __syncthreads();

    int t = t0 + threadIdx.x;
    float2 q = g_Q[b * TT + t];
    int s_limit = t - s0 + 1;
    if (s_limit > 1024) s_limit = 1024;

    float best = -CUDART_INF_F;
    int bi = 0;
    for (int s = 0; s < s_limit; ++s) {        // ascending + strict > = first occ.
        float2 k = ks[s];
        float sc = k.x * q.x + k.y * q.y;
        if (sc > best) { best = sc; bi = s0 + s; }
    }
    unsigned long long enc =
        ((unsigned long long)ord_f32(best) << 32) | (unsigned)(~bi);
    atomicMax(&g_best64[b * TT + t], enc);
}

// ---------------- kernel 2b: decode argmax + build unique list -------------
__global__ void decode_kernel() {
    int i = blockIdx.x * 256 + threadIdx.x;
    if (i >= NROW) return;
    unsigned long long enc = g_best64[i];
    int s = (int)(~(unsigned)(enc & 0xffffffffull));
    int src = (i & ~(TT - 1)) | s;
    g_idx[i] = src;
    if (atomicExch(&g_mark[src], 1) == 0) {
        int p = atomicAdd(&g_count, 1);
        if (p < SLOTS) {
            g_list[p] = src;
            g_slot[src] = p;                   // read only by later kernels
        }
    }
}

// ---------------- kernel 3: V rows, columnar (uses WVt) ----------------
// Item = (8-row group, 64-e tile, k-quarter): ngrp*64 items (~512).
// Block 128 thr; thread = (row = tid>>4, f4e = tid&15) owns acc4 over its
// k-quarter. Inner warp-iter: 1 broadcast LDS.32 + 1 coalesced LDG.128 of
// WVt + 4 FFMA. No shuffles, no reductions; acc4 written as k-partial.
#define RG 8
__global__ void __launch_bounds__(128) vrows_kernel(const float* __restrict__ x) {
    __shared__ float xs[RG * 256];             // 8 rows x 256-k chunk, 8 KB
    int cnt = g_count; if (cnt > SLOTS) cnt = SLOTS;
    int ngrp = (cnt + RG - 1) / RG;
    int items = ngrp * 64;                     // 16 e-tiles * 4 k-quarters
    int tid = threadIdx.x;
    int row = tid >> 4, f4e = tid & 15;

    for (int it = blockIdx.x; it < items; it += gridDim.x) {
        int kq  = it & 3;
        int et  = (it >> 2) & 15;
        int grp = it >> 6;
        int ui0 = grp * RG;
        int k0  = kq * 256;
        int E0  = et * 16;                     // float4-index base (64 e)

        __syncthreads();                       // protect xs reuse
#pragma unroll
        for (int j = 0; j < 4; ++j) {
            int f = tid + j * 128;             // 512 float4 total
            int r = f >> 6, c = f & 63;
            int ui = ui0 + r;
            int rw = g_list[(ui < cnt) ? ui : 0];
            ((float4*)xs)[f] = ((const float4*)x)[(size_t)rw * 256 + kq * 64 + c];
        }
        __syncthreads();

        const float4* wt = (const float4*)g_WVt;
        const float*  xr = xs + row * 256;
        float4 acc = make_float4(0.f, 0.f, 0.f, 0.f);
#pragma unroll 4
        for (int k = 0; k < 256; ++k) {
            float  xv = xr[k];                 // LDS.32 broadcast (2 addrs/warp)
            float4 w  = wt[(size_t)(k0 + k) * 256 + E0 + f4e];
            acc.x += xv * w.x;
            acc.y += xv * w.y;
            acc.z += xv * w.z;
            acc.w += xv * w.w;
        }
        int ui = ui0 + row;
        if (ui < cnt)
            ((float4*)g_Vp[kq])[(size_t)ui * 256 + E0 + f4e] = acc;
    }
}

// ---------------- kernel 3b: combine 4 k-partials -> compact V ------------
__global__ void combine_kernel() {
    int cnt = g_count; if (cnt > SLOTS) cnt = SLOTS;
    int n = cnt * 256;                         // float4 count
    for (int i = blockIdx.x * 256 + threadIdx.x; i < n; i += gridDim.x * 256) {
        float4 a = ((const float4*)g_Vp[0])[i];
        float4 b = ((const float4*)g_Vp[1])[i];
        float4 c = ((const float4*)g_Vp[2])[i];
        float4 d = ((const float4*)g_Vp[3])[i];
        float4 s;
        s.x = (a.x + b.x) + (c.x + d.x);
        s.y = (a.y + b.y) + (c.y + d.y);
        s.z = (a.z + b.z) + (c.z + d.z);
        s.w = (a.w + b.w) + (c.w + d.w);
        ((float4*)g_Vc)[i] = s;
    }
}

// ---------------- kernel 4: gather to output ----------------
// Warp copies one 4KB row from compact (L2-resident) V; streaming stores.
__global__ void gather_kernel(float* __restrict__ out) {
    int warp = threadIdx.x >> 5, lane = threadIdx.x & 31;
    int r = blockIdx.x * 8 + warp;          // destination row b*T + t
    int slot = g_slot[g_idx[r]];
    const float4* v4 = (const float4*)g_Vc + (size_t)slot * 256;
    float4* o4 = (float4*)out + (size_t)r * 256;
#pragma unroll
    for (int j = 0; j < 8; ++j) {
        float4 v = __ldg(&v4[lane + j * 32]);
        __stcs(&o4[lane + j * 32], v);
    }
}

extern "C" void kernel_launch(void* const* d_in, const int* in_sizes, int n_in,
                              void* d_out, int out_size) {
    const float* x  = (const float*)d_in[0];
    const float* WQ = (const float*)d_in[1];
    const float* WK = (const float*)d_in[2];
    const float* WV = (const float*)d_in[3];
    float* out = (float*)d_out;

    transpose_kernel<<<dim3(32, 32), dim3(32, 8)>>>(WV);
    qk_kernel<<<NROW / 8, 256>>>(x, WQ, WK);
    argmax_kernel<<<dim3(80, BB), 128>>>();
    decode_kernel<<<NROW / 256, 256>>>();
    vrows_kernel<<<592, 128>>>(x);
    combine_kernel<<<148, 256>>>();
    gather_kernel<<<NROW / 8, 256>>>(out);
}

// round 10
// speedup vs baseline: 1.2830x; 1.2752x over previous
#include <cuda_runtime.h>
#include <math_constants.h>

#define BB 4
#define TT 4096
#define DD 1024
#define NROW (BB*TT)          // 16384

// ---- scratch (device globals: no allocations allowed) ----
__device__ float2 g_Q[NROW];
__device__ float2 g_K[NROW];
__device__ unsigned long long g_best64[NROW]; // (ordered(score)<<32)|~s
__device__ int    g_idx[NROW];      // flattened source row b*T + argmax_s
__device__ int    g_mark[NROW];
__device__ int    g_slot[NROW];     // src row -> compact slot
__device__ int    g_list[NROW];
__device__ int    g_count;
__device__ float  g_Vc[(size_t)NROW * DD];  // compact V rows (slot-major)

static const unsigned FULL = 0xffffffffu;

__device__ __forceinline__ unsigned ord_f32(float x) {
    unsigned u = __float_as_uint(x);
    return (u & 0x80000000u) ? ~u : (u | 0x80000000u);
}

// ---------------- kernel 1: Q,K projection (+ fused scratch init) ----------
__global__ void qk_kernel(const float* __restrict__ x,
                          const float* __restrict__ WQ,
                          const float* __restrict__ WK) {
    __shared__ float4 swq0[256], swq1[256], swk0[256], swk1[256];
    const float4* WQ4 = (const float4*)WQ;
    const float4* WK4 = (const float4*)WK;
    int tid = threadIdx.x;
    swq0[tid] = WQ4[tid];
    swq1[tid] = WQ4[256 + tid];
    swk0[tid] = WK4[tid];
    swk1[tid] = WK4[256 + tid];
    __syncthreads();

    int warp = tid >> 5, lane = tid & 31;
    int row = blockIdx.x * 8 + warp;           // b*T + t
    const float4* x4 = (const float4*)x + (size_t)row * 256;

    float q0 = 0.f, q1 = 0.f, k0 = 0.f, k1 = 0.f;
#pragma unroll
    for (int j = 0; j < 8; ++j) {
        int d = lane + j * 32;
        float4 xv = x4[d];
        float4 a = swq0[d], b = swq1[d], c = swk0[d], e = swk1[d];
        q0 += xv.x*a.x + xv.y*a.y + xv.z*a.z + xv.w*a.w;
        q1 += xv.x*b.x + xv.y*b.y + xv.z*b.z + xv.w*b.w;
        k0 += xv.x*c.x + xv.y*c.y + xv.z*c.z + xv.w*c.w;
        k1 += xv.x*e.x + xv.y*e.y + xv.z*e.z + xv.w*e.w;
    }
#pragma unroll
    for (int off = 16; off; off >>= 1) {
        q0 += __shfl_xor_sync(FULL, q0, off);
        q1 += __shfl_xor_sync(FULL, q1, off);
        k0 += __shfl_xor_sync(FULL, k0, off);
        k1 += __shfl_xor_sync(FULL, k1, off);
    }
    if (lane == 0) {
        g_Q[row] = make_float2(q0, q1);
        g_K[row] = make_float2(k0, k1);
        g_mark[row] = 0;
        g_best64[row] = 0ull;                  // < any real score encoding
        if (row == 0) g_count = 0;
    }
}

// ---------------- kernel 2: argmax, paired-t tile x chunk units -------------
// Unit = (256-t tile, 1024-s chunk): 40 units/batch, grid (40, BB), 128 thr.
// Thread owns t and t+128; shared s-loop split into [0,la) both / [la,lb) b-only.
// Merge via atomicMax of (ordered(score)<<32)|~s  -> max score, min s on tie.
__global__ void __launch_bounds__(128) argmax_kernel() {
    __shared__ float2 ks[1024];    // 8 KB
    int b = blockIdx.y;
    // tiles of 256 t; tile ti has (ti>>2)+1 chunks; group g holds 4 tiles.
    int u = blockIdx.x, g = 0, base = 0;
    while (u >= base + 4 * (g + 1)) { base += 4 * (g + 1); ++g; }
    int r = u - base;
    int ti = g * 4 + r / (g + 1);
    int chunk = r % (g + 1);
    int t0 = ti * 256, s0 = chunk * 1024;

    const float4* K4 = (const float4*)(g_K + b * TT + s0);
#pragma unroll
    for (int j = 0; j < 4; ++j)
        ((float4*)ks)[threadIdx.x + j * 128] = K4[threadIdx.x + j * 128];
    __syncthreads();

    int ta = t0 + threadIdx.x;
    int tb = ta + 128;
    float2 qa = g_Q[b * TT + ta];
    float2 qb = g_Q[b * TT + tb];
    int la = ta - s0 + 1; if (la > 1024) la = 1024;   // >=1 by construction
    int lb = tb - s0 + 1; if (lb > 1024) lb = 1024;

    float ba = -CUDART_INF_F, bb = -CUDART_INF_F;
    int ia = 0, ib = 0;
    int s = 0;
    for (; s < la; ++s) {                      // both t's causal here
        float2 k = ks[s];
        float sa = k.x * qa.x + k.y * qa.y;
        float sb = k.x * qb.x + k.y * qb.y;
        if (sa > ba) { ba = sa; ia = s0 + s; }
        if (sb > bb) { bb = sb; ib = s0 + s; }
    }
    for (; s < lb; ++s) {                      // only tb causal
        float2 k = ks[s];
        float sb = k.x * qb.x + k.y * qb.y;
        if (sb > bb) { bb = sb; ib = s0 + s; }
    }
    unsigned long long ea =
        ((unsigned long long)ord_f32(ba) << 32) | (unsigned)(~ia);
    unsigned long long eb =
        ((unsigned long long)ord_f32(bb) << 32) | (unsigned)(~ib);
    atomicMax(&g_best64[b * TT + ta], ea);
    atomicMax(&g_best64[b * TT + tb], eb);
}

// ---------------- kernel 2b: decode argmax + build unique list -------------
// Warp-dedup (__match_any_sync) + mark prefilter: few atomics instead of 16K
// funneling into ~64 hot addresses.
__global__ void decode_kernel() {
    int i = blockIdx.x * 256 + threadIdx.x;
    unsigned long long enc = g_best64[i];
    int s = (int)(~(unsigned)(enc & 0xffffffffull));
    int src = (i & ~(TT - 1)) | s;
    g_idx[i] = src;

    unsigned peers = __match_any_sync(FULL, src);
    int leader = __ffs(peers) - 1;
    if ((threadIdx.x & 31) == leader) {
        if (g_mark[src] == 0 && atomicExch(&g_mark[src], 1) == 0) {
            int p = atomicAdd(&g_count, 1);
            g_list[p] = src;
            g_slot[src] = p;                   // read only by later kernels
        }
    }
}

// ---------------- kernel 3: V rows, 8 rows x 4 e per warp (R7) -------------
#define RG 8
__global__ void __launch_bounds__(256) vrows_kernel(const float* __restrict__ WV,
                                                    const float* __restrict__ x) {
    __shared__ float4 xs[RG * 256];            // 32 KB
    int cnt = g_count;
    int ngrp = (cnt + RG - 1) / RG;
    int items = ngrp * 32;                     // 32 e-tiles of 32
    int warp = threadIdx.x >> 5, lane = threadIdx.x & 31;

    for (int it = blockIdx.x; it < items; it += gridDim.x) {
        int grp  = it >> 5;                    // / 32
        int tile = it & 31;
        int ui0  = grp * RG;

        __syncthreads();                       // protect xs reuse
        {
            int ui = ui0 + warp;               // warp w loads row w
            int row = g_list[(ui < cnt) ? ui : 0];
            const float4* xr = (const float4*)x + (size_t)row * 256;
#pragma unroll
            for (int j = 0; j < 8; ++j)
                xs[warp * 256 + lane + j * 32] = xr[lane + j * 32];
        }
        __syncthreads();

        int e0 = tile * 32 + warp * 4;
        const float4* wp0 = (const float4*)WV + (size_t)(e0 + 0) * 256;
        const float4* wp1 = (const float4*)WV + (size_t)(e0 + 1) * 256;
        const float4* wp2 = (const float4*)WV + (size_t)(e0 + 2) * 256;
        const float4* wp3 = (const float4*)WV + (size_t)(e0 + 3) * 256;

        float a[32];                           // a[r*4+e]
#pragma unroll
        for (int k = 0; k < 32; ++k) a[k] = 0.f;

#pragma unroll
        for (int j = 0; j < 8; ++j) {
            int d = lane + j * 32;
            float4 w0 = __ldg(&wp0[d]);
            float4 w1 = __ldg(&wp1[d]);
            float4 w2 = __ldg(&wp2[d]);
            float4 w3 = __ldg(&wp3[d]);
#pragma unroll
            for (int r = 0; r < RG; ++r) {
                float4 xv = xs[r * 256 + d];
                a[r*4+0] += w0.x*xv.x + w0.y*xv.y + w0.z*xv.z + w0.w*xv.w;
                a[r*4+1] += w1.x*xv.x + w1.y*xv.y + w1.z*xv.z + w1.w*xv.w;
                a[r*4+2] += w2.x*xv.x + w2.y*xv.y + w2.z*xv.z + w2.w*xv.w;
                a[r*4+3] += w3.x*xv.x + w3.y*xv.y + w3.z*xv.z + w3.w*xv.w;
            }
        }

        // multi-value butterfly: 31 SHFL total; lane l ends with pair l.
#pragma unroll
        for (int off = 16; off; off >>= 1) {
#pragma unroll
            for (int i = 0; i < off; ++i) {
                float lo = a[i], hi = a[i + off];
                float mine = (lane & off) ? hi : lo;
                float send = (lane & off) ? lo : hi;
                float other = __shfl_xor_sync(FULL, send, off);
                a[i] = mine + other;
            }
        }

        int r = lane >> 2, e = lane & 3;
        int ui = ui0 + r;
        if (ui < cnt)
            g_Vc[(size_t)ui * DD + e0 + e] = a[0];
    }
}

// ---------------- kernel 4: gather to output ----------------
// Warp copies one 4KB row from compact (L2-resident) V; streaming stores.
__global__ void gather_kernel(float* __restrict__ out) {
    int warp = threadIdx.x >> 5, lane = threadIdx.x & 31;
    int r = blockIdx.x * 8 + warp;          // destination row b*T + t
    int slot = g_slot[g_idx[r]];
    const float4* v4 = (const float4*)g_Vc + (size_t)slot * 256;
    float4* o4 = (float4*)out + (size_t)r * 256;
#pragma unroll
    for (int j = 0; j < 8; ++j) {
        float4 v = __ldg(&v4[lane + j * 32]);
        __stcs(&o4[lane + j * 32], v);
    }
}

extern "C" void kernel_launch(void* const* d_in, const int* in_sizes, int n_in,
                              void* d_out, int out_size) {
    const float* x  = (const float*)d_in[0];
    const float* WQ = (const float*)d_in[1];
    const float* WK = (const float*)d_in[2];
    const float* WV = (const float*)d_in[3];
    float* out = (float*)d_out;

    qk_kernel<<<NROW / 8, 256>>>(x, WQ, WK);
    argmax_kernel<<<dim3(40, BB), 128>>>();
    decode_kernel<<<NROW / 256, 256>>>();
    vrows_kernel<<<444, 256>>>(WV, x);
    gather_kernel<<<NROW / 8, 256>>>(out);
}

// round 11
// speedup vs baseline: 1.4641x; 1.1412x over previous
#include <cuda_runtime.h>
#include <math_constants.h>

#define BB 4
#define TT 4096
#define DD 1024
#define NROW (BB*TT)          // 16384

// ---- scratch (device globals: no allocations allowed) ----
__device__ float2 g_Q[NROW];
__device__ float2 g_K[NROW];
__device__ unsigned long long g_best64[NROW]; // (ordered(score)<<32)|~s
__device__ int    g_idx[NROW];      // flattened source row b*T + argmax_s
__device__ int    g_mark[NROW];
__device__ int    g_slot[NROW];     // src row -> compact slot
__device__ int    g_list[NROW];
__device__ int    g_count;
__device__ float  g_Vc[(size_t)NROW * DD];  // compact V rows (slot-major)

static const unsigned FULL = 0xffffffffu;

__device__ __forceinline__ unsigned ord_f32(float x) {
    unsigned u = __float_as_uint(x);
    return (u & 0x80000000u) ? ~u : (u | 0x80000000u);
}

// ---------------- kernel 1: Q,K projection (+ fused scratch init) ----------
__global__ void qk_kernel(const float* __restrict__ x,
                          const float* __restrict__ WQ,
                          const float* __restrict__ WK) {
    __shared__ float4 swq0[256], swq1[256], swk0[256], swk1[256];
    const float4* WQ4 = (const float4*)WQ;
    const float4* WK4 = (const float4*)WK;
    int tid = threadIdx.x;
    swq0[tid] = WQ4[tid];
    swq1[tid] = WQ4[256 + tid];
    swk0[tid] = WK4[tid];
    swk1[tid] = WK4[256 + tid];
    __syncthreads();

    int warp = tid >> 5, lane = tid & 31;
    int row = blockIdx.x * 8 + warp;           // b*T + t
    const float4* x4 = (const float4*)x + (size_t)row * 256;

    float q0 = 0.f, q1 = 0.f, k0 = 0.f, k1 = 0.f;
#pragma unroll
    for (int j = 0; j < 8; ++j) {
        int d = lane + j * 32;
        float4 xv = x4[d];
        float4 a = swq0[d], b = swq1[d], c = swk0[d], e = swk1[d];
        q0 += xv.x*a.x + xv.y*a.y + xv.z*a.z + xv.w*a.w;
        q1 += xv.x*b.x + xv.y*b.y + xv.z*b.z + xv.w*b.w;
        k0 += xv.x*c.x + xv.y*c.y + xv.z*c.z + xv.w*c.w;
        k1 += xv.x*e.x + xv.y*e.y + xv.z*e.z + xv.w*e.w;
    }
#pragma unroll
    for (int off = 16; off; off >>= 1) {
        q0 += __shfl_xor_sync(FULL, q0, off);
        q1 += __shfl_xor_sync(FULL, q1, off);
        k0 += __shfl_xor_sync(FULL, k0, off);
        k1 += __shfl_xor_sync(FULL, k1, off);
    }
    if (lane == 0) {
        g_Q[row] = make_float2(q0, q1);
        g_K[row] = make_float2(k0, k1);
        g_mark[row] = 0;
        g_best64[row] = 0ull;                  // < any real score encoding
        if (row == 0) g_count = 0;
    }
}

// ---------------- kernel 2: argmax, tile x chunk units (R7 exact) ----------
// Unit = (128-t tile, 1024-s chunk). 80 units/batch, grid (80, BB), 128 thr.
// Merge via atomicMax of (ordered(score)<<32)|~s  -> max score, min s on tie.
__global__ void __launch_bounds__(128) argmax_kernel() {
    __shared__ float2 ks[1024];    // 8 KB
    int b = blockIdx.y;
    int u = blockIdx.x, g = 0, base = 0;
    while (u >= base + 8 * (g + 1)) { base += 8 * (g + 1); ++g; }
    int r = u - base;
    int ti = g * 8 + r / (g + 1);
    int chunk = r % (g + 1);
    int t0 = ti * 128, s0 = chunk * 1024;

    const float4* K4 = (const float4*)(g_K + b * TT + s0);
#pragma unroll
    for (int j = 0; j < 4; ++j)
        ((float4*)ks)[threadIdx.x + j * 128] = K4[threadIdx.x + j * 128];
    __syncthreads();

    int t = t0 + threadIdx.x;
    float2 q = g_Q[b * TT + t];
    int s_limit = t - s0 + 1;
    if (s_limit > 1024) s_limit = 1024;

    float best = -CUDART_INF_F;
    int bi = 0;
    for (int s = 0; s < s_limit; ++s) {        // ascending + strict > = first occ.
        float2 k = ks[s];
        float sc = k.x * q.x + k.y * q.y;
        if (sc > best) { best = sc; bi = s0 + s; }
    }
    unsigned long long enc =
        ((unsigned long long)ord_f32(best) << 32) | (unsigned)(~bi);
    atomicMax(&g_best64[b * TT + t], enc);
}

// ---------------- kernel 2b: decode argmax + build unique list -------------
// Warp-dedup (__match_any_sync) + mark prefilter: few atomics instead of 16K
// funneling into ~64 hot addresses.
__global__ void decode_kernel() {
    int i = blockIdx.x * 256 + threadIdx.x;
    unsigned long long enc = g_best64[i];
    int s = (int)(~(unsigned)(enc & 0xffffffffull));
    int src = (i & ~(TT - 1)) | s;
    g_idx[i] = src;

    unsigned peers = __match_any_sync(FULL, src);
    int leader = __ffs(peers) - 1;
    if ((threadIdx.x & 31) == leader) {
        if (g_mark[src] == 0 && atomicExch(&g_mark[src], 1) == 0) {
            int p = atomicAdd(&g_count, 1);
            g_list[p] = src;
            g_slot[src] = p;                   // read only by later kernels
        }
    }
}

// ---------------- kernel 3: V rows, 8 rows x 4 e per warp (R7) -------------
#define RG 8
__global__ void __launch_bounds__(256) vrows_kernel(const float* __restrict__ WV,
                                                    const float* __restrict__ x) {
    __shared__ float4 xs[RG * 256];            // 32 KB
    int cnt = g_count;
    int ngrp = (cnt + RG - 1) / RG;
    int items = ngrp * 32;                     // 32 e-tiles of 32
    int warp = threadIdx.x >> 5, lane = threadIdx.x & 31;

    for (int it = blockIdx.x; it < items; it += gridDim.x) {
        int grp  = it >> 5;                    // / 32
        int tile = it & 31;
        int ui0  = grp * RG;

        __syncthreads();                       // protect xs reuse
        {
            int ui = ui0 + warp;               // warp w loads row w
            int row = g_list[(ui < cnt) ? ui : 0];
            const float4* xr = (const float4*)x + (size_t)row * 256;
#pragma unroll
            for (int j = 0; j < 8; ++j)
                xs[warp * 256 + lane + j * 32] = xr[lane + j * 32];
        }
        __syncthreads();

        int e0 = tile * 32 + warp * 4;
        const float4* wp0 = (const float4*)WV + (size_t)(e0 + 0) * 256;
        const float4* wp1 = (const float4*)WV + (size_t)(e0 + 1) * 256;
        const float4* wp2 = (const float4*)WV + (size_t)(e0 + 2) * 256;
        const float4* wp3 = (const float4*)WV + (size_t)(e0 + 3) * 256;

        float a[32];                           // a[r*4+e]
#pragma unroll
        for (int k = 0; k < 32; ++k) a[k] = 0.f;

#pragma unroll
        for (int j = 0; j < 8; ++j) {
            int d = lane + j * 32;
            float4 w0 = __ldg(&wp0[d]);
            float4 w1 = __ldg(&wp1[d]);
            float4 w2 = __ldg(&wp2[d]);
            float4 w3 = __ldg(&wp3[d]);
#pragma unroll
            for (int r = 0; r < RG; ++r) {
                float4 xv = xs[r * 256 + d];
                a[r*4+0] += w0.x*xv.x + w0.y*xv.y + w0.z*xv.z + w0.w*xv.w;
                a[r*4+1] += w1.x*xv.x + w1.y*xv.y + w1.z*xv.z + w1.w*xv.w;
                a[r*4+2] += w2.x*xv.x + w2.y*xv.y + w2.z*xv.z + w2.w*xv.w;
                a[r*4+3] += w3.x*xv.x + w3.y*xv.y + w3.z*xv.z + w3.w*xv.w;
            }
        }

        // multi-value butterfly: 31 SHFL total; lane l ends with pair l.
#pragma unroll
        for (int off = 16; off; off >>= 1) {
#pragma unroll
            for (int i = 0; i < off; ++i) {
                float lo = a[i], hi = a[i + off];
                float mine = (lane & off) ? hi : lo;
                float send = (lane & off) ? lo : hi;
                float other = __shfl_xor_sync(FULL, send, off);
                a[i] = mine + other;
            }
        }

        int r = lane >> 2, e = lane & 3;
        int ui = ui0 + r;
        if (ui < cnt)
            g_Vc[(size_t)ui * DD + e0 + e] = a[0];
    }
}

// ---------------- kernel 4: gather to output ----------------
// Warp copies one 4KB row from compact (L2-resident) V; streaming stores.
__global__ void gather_kernel(float* __restrict__ out) {
    int warp = threadIdx.x >> 5, lane = threadIdx.x & 31;
    int r = blockIdx.x * 8 + warp;          // destination row b*T + t
    int slot = g_slot[g_idx[r]];
    const float4* v4 = (const float4*)g_Vc + (size_t)slot * 256;
    float4* o4 = (float4*)out + (size_t)r * 256;
#pragma unroll
    for (int j = 0; j < 8; ++j) {
        float4 v = __ldg(&v4[lane + j * 32]);
        __stcs(&o4[lane + j * 32], v);
    }
}

extern "C" void kernel_launch(void* const* d_in, const int* in_sizes, int n_in,
                              void* d_out, int out_size) {
    const float* x  = (const float*)d_in[0];
    const float* WQ = (const float*)d_in[1];
    const float* WK = (const float*)d_in[2];
    const float* WV = (const float*)d_in[3];
    float* out = (float*)d_out;

    qk_kernel<<<NROW / 8, 256>>>(x, WQ, WK);
    argmax_kernel<<<dim3(80, BB), 128>>>();
    decode_kernel<<<NROW / 256, 256>>>();
    vrows_kernel<<<444, 256>>>(WV, x);
    gather_kernel<<<NROW / 8, 256>>>(out);
}

// round 12
// speedup vs baseline: 1.5002x; 1.0246x over previous
#include <cuda_runtime.h>
#include <math_constants.h>

#define BB 4
#define TT 4096
#define DD 1024
#define NROW (BB*TT)          // 16384

// ---- scratch (device globals: no allocations allowed) ----
__device__ float2 g_Q[NROW];
__device__ float2 g_K[NROW];
__device__ unsigned long long g_best64[NROW]; // (ordered(score)<<32)|~s
__device__ int    g_idx[NROW];      // flattened source row b*T + argmax_s
__device__ int    g_mark[NROW];
__device__ int    g_slot[NROW];     // src row -> compact slot
__device__ int    g_list[NROW];
__device__ int    g_count;
__device__ float  g_Vc[(size_t)NROW * DD];  // compact V rows (slot-major)

static const unsigned FULL = 0xffffffffu;

__device__ __forceinline__ unsigned ord_f32(float x) {
    unsigned u = __float_as_uint(x);
    return (u & 0x80000000u) ? ~u : (u | 0x80000000u);
}

// ---------------- kernel 1: Q,K projection (+ fused scratch init) ----------
__global__ void qk_kernel(const float* __restrict__ x,
                          const float* __restrict__ WQ,
                          const float* __restrict__ WK) {
    __shared__ float4 swq0[256], swq1[256], swk0[256], swk1[256];
    const float4* WQ4 = (const float4*)WQ;
    const float4* WK4 = (const float4*)WK;
    int tid = threadIdx.x;
    swq0[tid] = WQ4[tid];
    swq1[tid] = WQ4[256 + tid];
    swk0[tid] = WK4[tid];
    swk1[tid] = WK4[256 + tid];
    __syncthreads();

    int warp = tid >> 5, lane = tid & 31;
    int row = blockIdx.x * 8 + warp;           // b*T + t
    const float4* x4 = (const float4*)x + (size_t)row * 256;

    float q0 = 0.f, q1 = 0.f, k0 = 0.f, k1 = 0.f;
#pragma unroll
    for (int j = 0; j < 8; ++j) {
        int d = lane + j * 32;
        float4 xv = x4[d];
        float4 a = swq0[d], b = swq1[d], c = swk0[d], e = swk1[d];
        q0 += xv.x*a.x + xv.y*a.y + xv.z*a.z + xv.w*a.w;
        q1 += xv.x*b.x + xv.y*b.y + xv.z*b.z + xv.w*b.w;
        k0 += xv.x*c.x + xv.y*c.y + xv.z*c.z + xv.w*c.w;
        k1 += xv.x*e.x + xv.y*e.y + xv.z*e.z + xv.w*e.w;
    }
#pragma unroll
    for (int off = 16; off; off >>= 1) {
        q0 += __shfl_xor_sync(FULL, q0, off);
        q1 += __shfl_xor_sync(FULL, q1, off);
        k0 += __shfl_xor_sync(FULL, k0, off);
        k1 += __shfl_xor_sync(FULL, k1, off);
    }
    if (lane == 0) {
        g_Q[row] = make_float2(q0, q1);
        g_K[row] = make_float2(k0, k1);
        g_mark[row] = 0;
        g_best64[row] = 0ull;                  // < any real score encoding
        if (row == 0) g_count = 0;
    }
}

// ---------------- kernel 2: argmax, tile x chunk units (R7 exact) ----------
// Unit = (128-t tile, 1024-s chunk). 80 units/batch, grid (80, BB), 128 thr.
// Merge via atomicMax of (ordered(score)<<32)|~s  -> max score, min s on tie.
__global__ void __launch_bounds__(128) argmax_kernel() {
    __shared__ float2 ks[1024];    // 8 KB
    int b = blockIdx.y;
    int u = blockIdx.x, g = 0, base = 0;
    while (u >= base + 8 * (g + 1)) { base += 8 * (g + 1); ++g; }
    int r = u - base;
    int ti = g * 8 + r / (g + 1);
    int chunk = r % (g + 1);
    int t0 = ti * 128, s0 = chunk * 1024;

    const float4* K4 = (const float4*)(g_K + b * TT + s0);
#pragma unroll
    for (int j = 0; j < 4; ++j)
        ((float4*)ks)[threadIdx.x + j * 128] = K4[threadIdx.x + j * 128];
    __syncthreads();

    int t = t0 + threadIdx.x;
    float2 q = g_Q[b * TT + t];
    int s_limit = t - s0 + 1;
    if (s_limit > 1024) s_limit = 1024;

    float best = -CUDART_INF_F;
    int bi = 0;
    for (int s = 0; s < s_limit; ++s) {        // ascending + strict > = first occ.
        float2 k = ks[s];
        float sc = k.x * q.x + k.y * q.y;
        if (sc > best) { best = sc; bi = s0 + s; }
    }
    unsigned long long enc =
        ((unsigned long long)ord_f32(best) << 32) | (unsigned)(~bi);
    atomicMax(&g_best64[b * TT + t], enc);
}

// ---------------- kernel 2b: decode argmax + build unique list -------------
// Warp-dedup (__match_any_sync) + mark prefilter: few atomics instead of 16K
// funneling into ~64 hot addresses.
__global__ void decode_kernel() {
    int i = blockIdx.x * 256 + threadIdx.x;
    unsigned long long enc = g_best64[i];
    int s = (int)(~(unsigned)(enc & 0xffffffffull));
    int src = (i & ~(TT - 1)) | s;
    g_idx[i] = src;

    unsigned peers = __match_any_sync(FULL, src);
    int leader = __ffs(peers) - 1;
    if ((threadIdx.x & 31) == leader) {
        if (g_mark[src] == 0 && atomicExch(&g_mark[src], 1) == 0) {
            int p = atomicAdd(&g_count, 1);
            g_list[p] = src;
            g_slot[src] = p;                   // read only by later kernels
        }
    }
}

// ---------------- kernel 3: V rows, 4 rows x 4 e per warp ----------------
// Item = (4-row group, 32-e tile): ceil(cnt/4)*32 items (~512) -> grid fully
// fed. Warp: 16 accumulators; per j-step 4 LDS.128 + 4 LDG.128 + 64 FFMA.
// Epilogue: 31-SHFL butterfly (16 values); lanes 0-15 write (r=l>>2, e=l&3).
#define RG 4
__global__ void __launch_bounds__(256) vrows_kernel(const float* __restrict__ WV,
                                                    const float* __restrict__ x) {
    __shared__ float4 xs[RG * 256];            // 16 KB
    int cnt = g_count;
    int ngrp = (cnt + RG - 1) / RG;
    int items = ngrp * 32;                     // 32 e-tiles of 32
    int warp = threadIdx.x >> 5, lane = threadIdx.x & 31;
    int tid = threadIdx.x;

    for (int it = blockIdx.x; it < items; it += gridDim.x) {
        int grp  = it >> 5;                    // / 32
        int tile = it & 31;
        int ui0  = grp * RG;

        __syncthreads();                       // protect xs reuse
#pragma unroll
        for (int j = 0; j < 4; ++j) {          // 1024 float4 by 256 threads
            int f = tid + j * 256;
            int r = f >> 8, c = f & 255;
            int ui = ui0 + r;
            int row = g_list[(ui < cnt) ? ui : 0];
            xs[f] = ((const float4*)x)[(size_t)row * 256 + c];
        }
        __syncthreads();

        int e0 = tile * 32 + warp * 4;
        const float4* wp0 = (const float4*)WV + (size_t)(e0 + 0) * 256;
        const float4* wp1 = (const float4*)WV + (size_t)(e0 + 1) * 256;
        const float4* wp2 = (const float4*)WV + (size_t)(e0 + 2) * 256;
        const float4* wp3 = (const float4*)WV + (size_t)(e0 + 3) * 256;

        float a[16];                           // a[r*4+e]
#pragma unroll
        for (int k = 0; k < 16; ++k) a[k] = 0.f;

#pragma unroll
        for (int j = 0; j < 8; ++j) {
            int d = lane + j * 32;
            float4 w0 = __ldg(&wp0[d]);
            float4 w1 = __ldg(&wp1[d]);
            float4 w2 = __ldg(&wp2[d]);
            float4 w3 = __ldg(&wp3[d]);
#pragma unroll
            for (int r = 0; r < RG; ++r) {
                float4 xv = xs[r * 256 + d];
                a[r*4+0] += w0.x*xv.x + w0.y*xv.y + w0.z*xv.z + w0.w*xv.w;
                a[r*4+1] += w1.x*xv.x + w1.y*xv.y + w1.z*xv.z + w1.w*xv.w;
                a[r*4+2] += w2.x*xv.x + w2.y*xv.y + w2.z*xv.z + w2.w*xv.w;
                a[r*4+3] += w3.x*xv.x + w3.y*xv.y + w3.z*xv.z + w3.w*xv.w;
            }
        }

        // butterfly: off=16 full-exchange on all 16, then distribute 16 values
        // over lanes (31 SHFL total). Lane l<16 ends with pair l.
#pragma unroll
        for (int i = 0; i < 16; ++i)
            a[i] += __shfl_xor_sync(FULL, a[i], 16);
#pragma unroll
        for (int off = 8; off; off >>= 1) {
#pragma unroll
            for (int i = 0; i < off; ++i) {
                float lo = a[i], hi = a[i + off];
                float mine = (lane & off) ? hi : lo;
                float send = (lane & off) ? lo : hi;
                float other = __shfl_xor_sync(FULL, send, off);
                a[i] = mine + other;
            }
        }

        if (lane < 16) {
            int r = lane >> 2, e = lane & 3;
            int ui = ui0 + r;
            if (ui < cnt)
                g_Vc[(size_t)ui * DD + e0 + e] = a[0];
        }
    }
}

// ---------------- kernel 4: gather to output ----------------
// Warp copies one 4KB row from compact (L2-resident) V; streaming stores.
__global__ void gather_kernel(float* __restrict__ out) {
    int warp = threadIdx.x >> 5, lane = threadIdx.x & 31;
    int r = blockIdx.x * 8 + warp;          // destination row b*T + t
    int slot = g_slot[g_idx[r]];
    const float4* v4 = (const float4*)g_Vc + (size_t)slot * 256;
    float4* o4 = (float4*)out + (size_t)r * 256;
#pragma unroll
    for (int j = 0; j < 8; ++j) {
        float4 v = __ldg(&v4[lane + j * 32]);
        __stcs(&o4[lane + j * 32], v);
    }
}

extern "C" void kernel_launch(void* const* d_in, const int* in_sizes, int n_in,
                              void* d_out, int out_size) {
    const float* x  = (const float*)d_in[0];
    const float* WQ = (const float*)d_in[1];
    const float* WK = (const float*)d_in[2];
    const float* WV = (const float*)d_in[3];
    float* out = (float*)d_out;

    qk_kernel<<<NROW / 8, 256>>>(x, WQ, WK);
    argmax_kernel<<<dim3(80, BB), 128>>>();
    decode_kernel<<<NROW / 256, 256>>>();
    vrows_kernel<<<444, 256>>>(WV, x);
    gather_kernel<<<NROW / 8, 256>>>(out);
}